// round 6
// baseline (speedup 1.0000x reference)
#include <cuda_runtime.h>
#include <math_constants.h>

#define BM 64
#define BN 64
#define KT 32
#define NMAX 16384
#define MARGIN 0.3f
#define EPS 1e-12f

__device__ float g_sq[NMAX];
__device__ float g_ap[NMAX];
__device__ float g_an[NMAX];
__device__ int   g_lab[NMAX];

// ---- canonicalize targets (int32 or int64 on disk) into g_lab as int32 ----
// Single block. Detect int64 by checking that the high 32-bit words (odd
// int32 indices) of the first 128 label slots are all zero.
__global__ void label_kernel(const int* __restrict__ traw, int n) {
    __shared__ int odd_nonzero;
    if (threadIdx.x == 0) odd_nonzero = 0;
    __syncthreads();
    int m = (n < 128) ? n : 128;
    for (int i = threadIdx.x; i < m; i += blockDim.x)
        if (traw[2 * i + 1] != 0) atomicOr(&odd_nonzero, 1);
    __syncthreads();
    bool is64 = (odd_nonzero == 0);
    for (int i = threadIdx.x; i < n; i += blockDim.x)
        g_lab[i] = is64 ? traw[2 * i] : traw[i];
}

// ---------------- squared norms: one warp per row ----------------
__global__ void sq_kernel(const float* __restrict__ X, int n, int d) {
    int warp = (blockIdx.x * blockDim.x + threadIdx.x) >> 5;
    int lane = threadIdx.x & 31;
    if (warp >= n) return;
    const float* row = X + (size_t)warp * d;
    float s = 0.f;
    for (int k = lane; k < d; k += 32) {
        float v = row[k];
        s = fmaf(v, v, s);
    }
    #pragma unroll
    for (int off = 16; off; off >>= 1)
        s += __shfl_xor_sync(0xffffffffu, s, off);
    if (lane == 0) g_sq[warp] = s;
}

// ---------------- fused gram + distance + hardest pos/neg ----------------
__global__ __launch_bounds__(256, 2)
void dist_kernel(const float* __restrict__ X, int n, int d) {
    __shared__ float As[KT][BM];
    __shared__ float Bs[KT][BN];
    __shared__ int   tR[BM];
    __shared__ float sR[BM];
    __shared__ int   tC[BN];
    __shared__ float sC[BN];

    const int tid = threadIdx.x;           // 256 threads
    const int tx = tid & 15;               // col group 0..15
    const int ty = tid >> 4;               // row group 0..15
    const int rowBase = blockIdx.x * BM;

    if (tid < BM) {
        int r = rowBase + tid;
        tR[tid] = (r < n) ? g_lab[r] : -1;
        sR[tid] = (r < n) ? g_sq[r] : 0.f;
    }
    __syncthreads();

    int   myT[4];
    float myS[4];
    float apv[4], anv[4];
    #pragma unroll
    for (int i = 0; i < 4; i++) {
        myT[i] = tR[ty * 4 + i];
        myS[i] = sR[ty * 4 + i];
        apv[i] = -CUDART_INF_F;
        anv[i] =  CUDART_INF_F;
    }

    const int kVec = KT / 4;               // float4 slots per row (8)

    for (int jt = 0; jt < n; jt += BN) {
        __syncthreads();                   // protect tC/sC reuse
        if (tid < BN) {
            int c = jt + tid;
            tC[tid] = (c < n) ? g_lab[c] : -2;
            sC[tid] = (c < n) ? g_sq[c] : 0.f;
        }

        float acc[4][4];
        #pragma unroll
        for (int i = 0; i < 4; i++)
            #pragma unroll
            for (int j = 0; j < 4; j++) acc[i][j] = 0.f;

        for (int kt = 0; kt < d; kt += KT) {
            __syncthreads();
            // load A tile (BM x KT) transposed into As[k][row]
            #pragma unroll
            for (int l = tid; l < BM * kVec; l += 256) {
                int r  = l / kVec;
                int kk = (l % kVec) * 4;
                float4 v = *(const float4*)&X[(size_t)(rowBase + r) * d + kt + kk];
                As[kk + 0][r] = v.x; As[kk + 1][r] = v.y;
                As[kk + 2][r] = v.z; As[kk + 3][r] = v.w;
            }
            // load B tile (BN x KT) transposed into Bs[k][col]
            #pragma unroll
            for (int l = tid; l < BN * kVec; l += 256) {
                int r  = l / kVec;
                int kk = (l % kVec) * 4;
                float4 v = *(const float4*)&X[(size_t)(jt + r) * d + kt + kk];
                Bs[kk + 0][r] = v.x; Bs[kk + 1][r] = v.y;
                Bs[kk + 2][r] = v.z; Bs[kk + 3][r] = v.w;
            }
            __syncthreads();

            #pragma unroll
            for (int k = 0; k < KT; k++) {
                float a[4], b[4];
                *(float4*)a = *(const float4*)&As[k][ty * 4];
                *(float4*)b = *(const float4*)&Bs[k][tx * 4];
                #pragma unroll
                for (int i = 0; i < 4; i++)
                    #pragma unroll
                    for (int j = 0; j < 4; j++)
                        acc[i][j] = fmaf(a[i], b[j], acc[i][j]);
            }
        }

        // epilogue: distances + hardest-positive / hardest-negative update
        #pragma unroll
        for (int j = 0; j < 4; j++) {
            int cidx = tx * 4 + j;
            int c = jt + cidx;
            bool valid = (c < n);
            int   tc = tC[cidx];
            float sc = sC[cidx];
            #pragma unroll
            for (int i = 0; i < 4; i++) {
                float d2 = myS[i] + sc - 2.f * acc[i][j];
                float dist = sqrtf(fmaxf(d2, EPS));
                bool same = (myT[i] == tc);
                if (valid) {
                    if (same) apv[i] = fmaxf(apv[i], dist);
                    else      anv[i] = fminf(anv[i], dist);
                }
            }
        }
    }

    // reduce across the 16 tx lanes (contiguous half-warp groups)
    #pragma unroll
    for (int off = 8; off; off >>= 1) {
        #pragma unroll
        for (int i = 0; i < 4; i++) {
            apv[i] = fmaxf(apv[i], __shfl_xor_sync(0xffffffffu, apv[i], off));
            anv[i] = fminf(anv[i], __shfl_xor_sync(0xffffffffu, anv[i], off));
        }
    }
    if (tx == 0) {
        #pragma unroll
        for (int i = 0; i < 4; i++) {
            int r = rowBase + ty * 4 + i;
            if (r < n) { g_ap[r] = apv[i]; g_an[r] = anv[i]; }
        }
    }
}

// ---------------- final mean(relu(ap - an + margin)) ----------------
__global__ void loss_kernel(int n, float* __restrict__ out) {
    __shared__ float red[1024];
    int tid = threadIdx.x;
    float s = 0.f;
    for (int i = tid; i < n; i += blockDim.x)
        s += fmaxf(g_ap[i] - g_an[i] + MARGIN, 0.f);
    red[tid] = s;
    __syncthreads();
    for (int off = blockDim.x >> 1; off; off >>= 1) {
        if (tid < off) red[tid] += red[tid + off];
        __syncthreads();
    }
    if (tid == 0) out[0] = red[0] / (float)n;
}

extern "C" void kernel_launch(void* const* d_in, const int* in_sizes, int n_in,
                              void* d_out, int out_size) {
    const float* X    = (const float*)d_in[0];
    const int*   traw = (const int*)d_in[1];
    float* out = (float*)d_out;
    int n = in_sizes[1];
    int d = in_sizes[0] / n;

    label_kernel<<<1, 256>>>(traw, n);

    int warpsPerBlock = 8;
    int nb = (n + warpsPerBlock - 1) / warpsPerBlock;
    sq_kernel<<<nb, warpsPerBlock * 32>>>(X, n, d);

    int rowBlocks = (n + BM - 1) / BM;
    dist_kernel<<<rowBlocks, 256>>>(X, n, d);

    loss_kernel<<<1, 1024>>>(n, out);
}

// round 8
// speedup vs baseline: 4.9900x; 4.9900x over previous
#include <cuda_runtime.h>
#include <math_constants.h>
#include <cstdint>

#define NMAX 16384
#define MARGIN 0.3f
#define EPS 1e-12f

#define TM 128
#define TN 128
#define KC 32
#define SPAD 36            // smem row stride in floats (conflict-free)
#define COLSPLIT 2

__device__ float g_sq[NMAX];
__device__ int   g_lab[NMAX];
__device__ int   g_ap_bits[NMAX];   // d^2 float bits; atomicMax valid for >=0 floats
__device__ int   g_an_bits[NMAX];   // d^2 float bits; atomicMin valid for >=0 floats

// ---- canonicalize targets (int32 or int64 on disk) into g_lab as int32 ----
__global__ void label_kernel(const int* __restrict__ traw, int n) {
    __shared__ int odd_nonzero;
    if (threadIdx.x == 0) odd_nonzero = 0;
    __syncthreads();
    int m = (n < 128) ? n : 128;
    for (int i = threadIdx.x; i < m; i += blockDim.x)
        if (traw[2 * i + 1] != 0) atomicOr(&odd_nonzero, 1);
    __syncthreads();
    bool is64 = (odd_nonzero == 0);
    for (int i = threadIdx.x; i < n; i += blockDim.x)
        g_lab[i] = is64 ? traw[2 * i] : traw[i];
}

// ---------------- squared norms (exact fp32): one warp per row ------------
__global__ void sq_kernel(const float* __restrict__ X, int n, int d) {
    int warp = (blockIdx.x * blockDim.x + threadIdx.x) >> 5;
    int lane = threadIdx.x & 31;
    if (warp >= n) return;
    const float4* row = (const float4*)(X + (size_t)warp * d);
    float s = 0.f;
    for (int k = lane; k < d / 4; k += 32) {
        float4 v = row[k];
        s = fmaf(v.x, v.x, s); s = fmaf(v.y, v.y, s);
        s = fmaf(v.z, v.z, s); s = fmaf(v.w, v.w, s);
    }
    #pragma unroll
    for (int off = 16; off; off >>= 1)
        s += __shfl_xor_sync(0xffffffffu, s, off);
    if (lane == 0) g_sq[warp] = s;
}

__global__ void init_kernel(int n) {
    int i = blockIdx.x * blockDim.x + threadIdx.x;
    if (i < n) { g_ap_bits[i] = 0; g_an_bits[i] = 0x7f800000; }
}

__device__ __forceinline__ uint32_t f2tf32(float f) {
    uint32_t u;
    asm("cvt.rna.tf32.f32 %0, %1;" : "=r"(u) : "f"(f));
    return u;
}

__device__ __forceinline__ void mma_tf32(float* c, const uint32_t* a, const uint32_t* b) {
    asm volatile(
        "mma.sync.aligned.m16n8k8.row.col.f32.tf32.tf32.f32 "
        "{%0,%1,%2,%3}, {%4,%5,%6,%7}, {%8,%9}, {%0,%1,%2,%3};"
        : "+f"(c[0]), "+f"(c[1]), "+f"(c[2]), "+f"(c[3])
        : "r"(a[0]), "r"(a[1]), "r"(a[2]), "r"(a[3]), "r"(b[0]), "r"(b[1]));
}

// --------- fused tf32 mma.sync gram + d^2 + hardest pos/neg ---------------
__global__ __launch_bounds__(256, 1)
void dist_mma_kernel(const float* __restrict__ X, int n, int d) {
    __shared__ uint32_t As[TM][SPAD];
    __shared__ uint32_t Bs[TN][SPAD];
    __shared__ int   tCs[TN];
    __shared__ float sCs[TN];

    const int tid  = threadIdx.x;          // 256 threads = 8 warps
    const int wid  = tid >> 5;
    const int lane = tid & 31;
    const int wm   = wid & 1;              // 2 warps along M
    const int wn   = wid >> 1;             // 4 warps along N
    const int gID  = lane >> 2;            // groupID
    const int tig  = lane & 3;             // thread-in-group

    const int rowBase = blockIdx.x * TM;
    const int colBase = blockIdx.y * (n / COLSPLIT);
    const int nJt = (n / COLSPLIT) / TN;

    // this thread's 8 output rows: (ma 0..3) x (h 0..1)
    int   rowT[8]; float rowS[8];
    #pragma unroll
    for (int ma = 0; ma < 4; ma++)
        #pragma unroll
        for (int h = 0; h < 2; h++) {
            int rg = rowBase + wm * 64 + ma * 16 + gID + 8 * h;
            rowT[ma * 2 + h] = g_lab[rg];
            rowS[ma * 2 + h] = g_sq[rg];
        }

    float apd2[8], and2[8];
    #pragma unroll
    for (int i = 0; i < 8; i++) { apd2[i] = 0.f; and2[i] = CUDART_INF_F; }

    for (int jt = 0; jt < nJt; jt++) {
        const int cTile = colBase + jt * TN;
        __syncthreads();                   // prev epilogue done reading tCs/sCs
        if (tid < TN) {
            tCs[tid] = g_lab[cTile + tid];
            sCs[tid] = g_sq[cTile + tid];
        }

        float acc[4][4][4];
        #pragma unroll
        for (int ma = 0; ma < 4; ma++)
            #pragma unroll
            for (int na = 0; na < 4; na++)
                #pragma unroll
                for (int f = 0; f < 4; f++) acc[ma][na][f] = 0.f;

        for (int kc = 0; kc < d; kc += KC) {
            __syncthreads();               // prev k-step LDS done before refill
            // fill As/Bs (128x32 each) as tf32; float4 loads, uint4 stores
            #pragma unroll
            for (int i = 0; i < 4; i++) {
                int fi = i * 256 + tid;    // float4 index
                int r  = fi >> 3;
                int q  = fi & 7;
                float4 va = *(const float4*)&X[(size_t)(rowBase + r) * d + kc + q * 4];
                float4 vb = *(const float4*)&X[(size_t)(cTile   + r) * d + kc + q * 4];
                uint4 ua = make_uint4(f2tf32(va.x), f2tf32(va.y), f2tf32(va.z), f2tf32(va.w));
                uint4 ub = make_uint4(f2tf32(vb.x), f2tf32(vb.y), f2tf32(vb.z), f2tf32(vb.w));
                *(uint4*)&As[r][q * 4] = ua;
                *(uint4*)&Bs[r][q * 4] = ub;
            }
            __syncthreads();

            #pragma unroll
            for (int k8 = 0; k8 < KC / 8; k8++) {
                const int kk = k8 * 8;
                uint32_t a[4][4], b[4][2];
                #pragma unroll
                for (int ma = 0; ma < 4; ma++) {
                    int r0 = wm * 64 + ma * 16 + gID;
                    a[ma][0] = As[r0    ][kk + tig];
                    a[ma][1] = As[r0 + 8][kk + tig];
                    a[ma][2] = As[r0    ][kk + 4 + tig];
                    a[ma][3] = As[r0 + 8][kk + 4 + tig];
                }
                #pragma unroll
                for (int na = 0; na < 4; na++) {
                    int c0 = wn * 32 + na * 8 + gID;
                    b[na][0] = Bs[c0][kk + tig];
                    b[na][1] = Bs[c0][kk + 4 + tig];
                }
                #pragma unroll
                for (int ma = 0; ma < 4; ma++)
                    #pragma unroll
                    for (int na = 0; na < 4; na++)
                        mma_tf32(acc[ma][na], a[ma], b[na]);
            }
        }

        // epilogue in d^2 domain (sqrt deferred; monotone so max/min commute)
        #pragma unroll
        for (int ma = 0; ma < 4; ma++)
            #pragma unroll
            for (int na = 0; na < 4; na++)
                #pragma unroll
                for (int f = 0; f < 4; f++) {
                    int h = f >> 1, j = f & 1;
                    int ridx = ma * 2 + h;
                    int col  = wn * 32 + na * 8 + tig * 2 + j;
                    int cg   = cTile + col;
                    int rg   = rowBase + wm * 64 + ma * 16 + gID + 8 * h;
                    float d2 = rowS[ridx] + sCs[col] - 2.f * acc[ma][na][f];
                    if (cg == rg) d2 = EPS;
                    d2 = fmaxf(d2, EPS);
                    if (rowT[ridx] == tCs[col]) apd2[ridx] = fmaxf(apd2[ridx], d2);
                    else                        and2[ridx] = fminf(and2[ridx], d2);
                }
    }

    // reduce across the 4 threads of each quad (same rows, different cols)
    #pragma unroll
    for (int off = 1; off <= 2; off <<= 1)
        #pragma unroll
        for (int i = 0; i < 8; i++) {
            apd2[i] = fmaxf(apd2[i], __shfl_xor_sync(0xffffffffu, apd2[i], off));
            and2[i] = fminf(and2[i], __shfl_xor_sync(0xffffffffu, and2[i], off));
        }
    if (tig == 0) {
        #pragma unroll
        for (int ma = 0; ma < 4; ma++)
            #pragma unroll
            for (int h = 0; h < 2; h++) {
                int rg = rowBase + wm * 64 + ma * 16 + gID + 8 * h;
                atomicMax(&g_ap_bits[rg], __float_as_int(apd2[ma * 2 + h]));
                atomicMin(&g_an_bits[rg], __float_as_int(and2[ma * 2 + h]));
            }
    }
}

// ---------------- final mean(relu(sqrt(ap2) - sqrt(an2) + margin)) --------
__global__ void loss_kernel(int n, float* __restrict__ out) {
    __shared__ float red[1024];
    int tid = threadIdx.x;
    float s = 0.f;
    for (int i = tid; i < n; i += blockDim.x) {
        float ap = sqrtf(fmaxf(__int_as_float(g_ap_bits[i]), EPS));
        float an = sqrtf(fmaxf(__int_as_float(g_an_bits[i]), EPS));
        s += fmaxf(ap - an + MARGIN, 0.f);
    }
    red[tid] = s;
    __syncthreads();
    for (int off = blockDim.x >> 1; off; off >>= 1) {
        if (tid < off) red[tid] += red[tid + off];
        __syncthreads();
    }
    if (tid == 0) out[0] = red[0] / (float)n;
}

extern "C" void kernel_launch(void* const* d_in, const int* in_sizes, int n_in,
                              void* d_out, int out_size) {
    const float* X    = (const float*)d_in[0];
    const int*   traw = (const int*)d_in[1];
    float* out = (float*)d_out;
    int n = in_sizes[1];
    int d = in_sizes[0] / n;

    label_kernel<<<1, 256>>>(traw, n);

    int warpsPerBlock = 8;
    int nb = (n + warpsPerBlock - 1) / warpsPerBlock;
    sq_kernel<<<nb, warpsPerBlock * 32>>>(X, n, d);

    init_kernel<<<(n + 255) / 256, 256>>>(n);

    dim3 grid(n / TM, COLSPLIT);
    dist_mma_kernel<<<grid, 256>>>(X, n, d);

    loss_kernel<<<1, 1024>>>(n, out);
}

// round 9
// speedup vs baseline: 5.9807x; 1.1985x over previous
#include <cuda_runtime.h>
#include <cuda_fp16.h>
#include <math_constants.h>
#include <cstdint>

#define NMAX 16384
#define MARGIN 0.3f
#define EPS 1e-12f

#define TM 128
#define TN 128
#define KC 64              // floats per stage (4 k16 blocks)
#define COLSPLIT 2

__device__ float g_sq[NMAX];
__device__ int   g_lab[NMAX];
__device__ int   g_ap_bits[NMAX];   // d^2 bits; atomicMax valid for >=0 floats
__device__ int   g_an_bits[NMAX];

// ---- canonicalize targets (int32 or int64 on disk) into g_lab as int32 ----
__global__ void label_kernel(const int* __restrict__ traw, int n) {
    __shared__ int odd_nonzero;
    if (threadIdx.x == 0) odd_nonzero = 0;
    __syncthreads();
    int m = (n < 128) ? n : 128;
    for (int i = threadIdx.x; i < m; i += blockDim.x)
        if (traw[2 * i + 1] != 0) atomicOr(&odd_nonzero, 1);
    __syncthreads();
    bool is64 = (odd_nonzero == 0);
    for (int i = threadIdx.x; i < n; i += blockDim.x)
        g_lab[i] = is64 ? traw[2 * i] : traw[i];
}

// ---------------- squared norms (exact fp32) ----------------
__global__ void sq_kernel(const float* __restrict__ X, int n, int d) {
    int warp = (blockIdx.x * blockDim.x + threadIdx.x) >> 5;
    int lane = threadIdx.x & 31;
    if (warp >= n) return;
    const float4* row = (const float4*)(X + (size_t)warp * d);
    float s = 0.f;
    for (int k = lane; k < d / 4; k += 32) {
        float4 v = row[k];
        s = fmaf(v.x, v.x, s); s = fmaf(v.y, v.y, s);
        s = fmaf(v.z, v.z, s); s = fmaf(v.w, v.w, s);
    }
    #pragma unroll
    for (int off = 16; off; off >>= 1)
        s += __shfl_xor_sync(0xffffffffu, s, off);
    if (lane == 0) g_sq[warp] = s;
}

__global__ void init_kernel(int n) {
    int i = blockIdx.x * blockDim.x + threadIdx.x;
    if (i < n) { g_ap_bits[i] = 0; g_an_bits[i] = 0x7f800000; }
}

__device__ __forceinline__ uint32_t h2pk(float a, float b) {
    __half2 h = __floats2half2_rn(a, b);
    return *reinterpret_cast<uint32_t*>(&h);
}

__device__ __forceinline__ void mma_f16(float* c, uint32_t a0, uint32_t a1,
                                        uint32_t a2, uint32_t a3,
                                        uint32_t b0, uint32_t b1) {
    asm volatile(
        "mma.sync.aligned.m16n8k16.row.col.f32.f16.f16.f32 "
        "{%0,%1,%2,%3}, {%4,%5,%6,%7}, {%8,%9}, {%0,%1,%2,%3};"
        : "+f"(c[0]), "+f"(c[1]), "+f"(c[2]), "+f"(c[3])
        : "r"(a0), "r"(a1), "r"(a2), "r"(a3), "r"(b0), "r"(b1));
}

// Build 4 zipped 16B units (t=0..3) for one (row-pair, k16-block) from fp32 regs.
// Unit t holds: {rowR(c2t,c2t+1), rowR(c2t+8,c2t+9), rowR8(c2t,..), rowR8(c2t+8,..)}
__device__ __forceinline__ void make_units(const float4 v[4], const float4 w[4],
                                           uint4 u[4]) {
    uint32_t rlo[4] = { h2pk(v[0].x, v[0].y), h2pk(v[0].z, v[0].w),
                        h2pk(v[1].x, v[1].y), h2pk(v[1].z, v[1].w) };
    uint32_t rhi[4] = { h2pk(v[2].x, v[2].y), h2pk(v[2].z, v[2].w),
                        h2pk(v[3].x, v[3].y), h2pk(v[3].z, v[3].w) };
    uint32_t slo[4] = { h2pk(w[0].x, w[0].y), h2pk(w[0].z, w[0].w),
                        h2pk(w[1].x, w[1].y), h2pk(w[1].z, w[1].w) };
    uint32_t shi[4] = { h2pk(w[2].x, w[2].y), h2pk(w[2].z, w[2].w),
                        h2pk(w[3].x, w[3].y), h2pk(w[3].z, w[3].w) };
    #pragma unroll
    for (int t = 0; t < 4; t++) u[t] = make_uint4(rlo[t], rhi[t], slo[t], shi[t]);
}

// --------- fused fp16 mma gram + d^2 + hardest pos/neg, pipelined ----------
__global__ __launch_bounds__(256, 1)
void dist_mma_kernel(const float* __restrict__ X, int n, int d) {
    extern __shared__ char dyn[];
    __shared__ int   tCs[TN];
    __shared__ float sCs[TN];

    const int tid  = threadIdx.x;          // 256 threads = 8 warps
    const int wid  = tid >> 5;
    const int lane = tid & 31;
    const int wm   = wid & 1;              // 2 warps along M
    const int wn   = wid >> 1;             // 4 warps along N
    const int gID  = lane >> 2;
    const int tig  = lane & 3;

    const int rowBase = blockIdx.x * TM;
    const int colBase = blockIdx.y * (n / COLSPLIT);
    const int nJt  = (n / COLSPLIT) / TN;
    const int nStA = d / KC;               // A stages (8 for d=512)
    char* dynA = dyn;
    char* dynB = dyn + nStA * 16384;

    // fill task mapping (conflict-free STS phases: 8 rows per 8-lane group)
    const int fp   = wid * 8 + (lane & 7); // row-pair index 0..63
    const int fblk = lane >> 3;            // k16 block 0..3
    const int frow = (fp >> 3) * 16 + (fp & 7);   // low row of the pair

    // ---------------- A fill: persistent, all nStA stages ----------------
    for (int st = 0; st < nStA; st++) {
        float4 v[4], w[4];
        const float* s0 = X + (size_t)(rowBase + frow) * d + st * KC + fblk * 16;
        const float* s1 = s0 + (size_t)8 * d;
        #pragma unroll
        for (int q = 0; q < 4; q++) { v[q] = *(const float4*)(s0 + q * 4);
                                      w[q] = *(const float4*)(s1 + q * 4); }
        uint4 u[4];
        make_units(v, w, u);
        char* base = dynA + st * 16384 + fp * 256;
        #pragma unroll
        for (int t = 0; t < 4; t++)
            *(uint4*)(base + (((4 * t + fblk) ^ (fp & 7)) << 4)) = u[t];
    }

    // ---------------- prologue: B stage 0 ----------------
    {
        float4 v[4], w[4];
        const float* s0 = X + (size_t)(colBase + frow) * d + fblk * 16;
        const float* s1 = s0 + (size_t)8 * d;
        #pragma unroll
        for (int q = 0; q < 4; q++) { v[q] = *(const float4*)(s0 + q * 4);
                                      w[q] = *(const float4*)(s1 + q * 4); }
        uint4 u[4];
        make_units(v, w, u);
        char* base = dynB + fp * 256;
        #pragma unroll
        for (int t = 0; t < 4; t++) {
            uint4 uu = (t < 2) ? u[t] : make_uint4(u[t].z, u[t].w, u[t].x, u[t].y);
            *(uint4*)(base + (((4 * t + fblk) ^ (fp & 7)) << 4)) = uu;
        }
    }

    // per-thread row metadata (8 output rows)
    int rowT[8]; float rowS[8];
    #pragma unroll
    for (int ma = 0; ma < 4; ma++)
        #pragma unroll
        for (int h = 0; h < 2; h++) {
            int rg = rowBase + wm * 64 + ma * 16 + gID + 8 * h;
            rowT[ma * 2 + h] = g_lab[rg];
            rowS[ma * 2 + h] = g_sq[rg];
        }

    // frag pair-offsets (bytes) — constant per thread
    int aPO[4], bPO[4];
    #pragma unroll
    for (int ma = 0; ma < 4; ma++) aPO[ma] = ((wm * 4 + ma) * 8 + gID) * 256;
    #pragma unroll
    for (int na = 0; na < 4; na++) bPO[na] = ((wn * 2 + (na >> 1)) * 8 + gID) * 256;
    const int hPar = ((tig >> 1) & 1) << 3;   // B half-select parity term

    float apd2[8], and2[8];
    #pragma unroll
    for (int i = 0; i < 8; i++) { apd2[i] = 0.f; and2[i] = CUDART_INF_F; }

    float acc[4][4][4];
    #pragma unroll
    for (int ma = 0; ma < 4; ma++)
        #pragma unroll
        for (int na = 0; na < 4; na++)
            #pragma unroll
            for (int f = 0; f < 4; f++) acc[ma][na][f] = 0.f;

    const int total = nJt * nStA;
    for (int s = 0; s < total; s++) {
        const int kcIdx = s & (nStA - 1);
        const int jt    = s >> 3;            // nStA == 8
        const int cTile = colBase + jt * TN;
        __syncthreads();                     // buf[s&1] + (first iter) fills visible

        if (kcIdx == 0 && tid < TN) {
            tCs[tid] = g_lab[cTile + tid];
            sCs[tid] = g_sq[cTile + tid];
        }

        // prefetch LDG for B stage s+1
        const bool pf = (s + 1 < total);
        float4 pv[4], pw[4];
        if (pf) {
            int s2 = s + 1;
            int cT2 = colBase + (s2 >> 3) * TN;
            int kc2 = (s2 & (nStA - 1)) * KC;
            const float* s0 = X + (size_t)(cT2 + frow) * d + kc2 + fblk * 16;
            const float* s1 = s0 + (size_t)8 * d;
            #pragma unroll
            for (int q = 0; q < 4; q++) { pv[q] = *(const float4*)(s0 + q * 4);
                                          pw[q] = *(const float4*)(s1 + q * 4); }
        }

        // ---- MMA over 4 k16 blocks of this stage ----
        const char* Ast = dynA + kcIdx * 16384;
        const char* Bst = dynB + (s & 1) * 16384;
        #pragma unroll
        for (int blk = 0; blk < 4; blk++) {
            const int colx = ((4 * tig + blk) ^ gID) << 4;
            uint4 af[4];
            #pragma unroll
            for (int ma = 0; ma < 4; ma++)
                af[ma] = *(const uint4*)(Ast + aPO[ma] + colx);
            uint2 bf[4];
            #pragma unroll
            for (int na = 0; na < 4; na++)
                bf[na] = *(const uint2*)(Bst + bPO[na] + colx + (((na & 1) << 3) ^ hPar));
            #pragma unroll
            for (int ma = 0; ma < 4; ma++)
                #pragma unroll
                for (int na = 0; na < 4; na++)
                    mma_f16(acc[ma][na], af[ma].x, af[ma].z, af[ma].y, af[ma].w,
                            bf[na].x, bf[na].y);
        }

        // ---- convert + STS B stage s+1 (other buffer) ----
        if (pf) {
            uint4 u[4];
            make_units(pv, pw, u);
            char* base = dynB + ((s + 1) & 1) * 16384 + fp * 256;
            #pragma unroll
            for (int t = 0; t < 4; t++) {
                uint4 uu = (t < 2) ? u[t] : make_uint4(u[t].z, u[t].w, u[t].x, u[t].y);
                *(uint4*)(base + (((4 * t + fblk) ^ (fp & 7)) << 4)) = uu;
            }
        }

        // ---- epilogue at last k-stage of this jt ----
        if (kcIdx == nStA - 1) {
            #pragma unroll
            for (int ma = 0; ma < 4; ma++)
                #pragma unroll
                for (int na = 0; na < 4; na++)
                    #pragma unroll
                    for (int f = 0; f < 4; f++) {
                        int h = f >> 1, j = f & 1;
                        int ridx = ma * 2 + h;
                        int col  = wn * 32 + na * 8 + tig * 2 + j;
                        int cg   = cTile + col;
                        int rg   = rowBase + wm * 64 + ma * 16 + gID + 8 * h;
                        float d2 = rowS[ridx] + sCs[col] - 2.f * acc[ma][na][f];
                        if (cg == rg) d2 = EPS;
                        d2 = fmaxf(d2, EPS);
                        if (rowT[ridx] == tCs[col]) apd2[ridx] = fmaxf(apd2[ridx], d2);
                        else                        and2[ridx] = fminf(and2[ridx], d2);
                        acc[ma][na][f] = 0.f;
                    }
        }
    }

    // reduce across the quad (same rows, different cols)
    #pragma unroll
    for (int off = 1; off <= 2; off <<= 1)
        #pragma unroll
        for (int i = 0; i < 8; i++) {
            apd2[i] = fmaxf(apd2[i], __shfl_xor_sync(0xffffffffu, apd2[i], off));
            and2[i] = fminf(and2[i], __shfl_xor_sync(0xffffffffu, and2[i], off));
        }
    if (tig == 0) {
        #pragma unroll
        for (int ma = 0; ma < 4; ma++)
            #pragma unroll
            for (int h = 0; h < 2; h++) {
                int rg = rowBase + wm * 64 + ma * 16 + gID + 8 * h;
                atomicMax(&g_ap_bits[rg], __float_as_int(apd2[ma * 2 + h]));
                atomicMin(&g_an_bits[rg], __float_as_int(and2[ma * 2 + h]));
            }
    }
}

// ---------------- final mean(relu(sqrt(ap2) - sqrt(an2) + margin)) --------
__global__ void loss_kernel(int n, float* __restrict__ out) {
    __shared__ float red[1024];
    int tid = threadIdx.x;
    float s = 0.f;
    for (int i = tid; i < n; i += blockDim.x) {
        float ap = sqrtf(fmaxf(__int_as_float(g_ap_bits[i]), EPS));
        float an = sqrtf(fmaxf(__int_as_float(g_an_bits[i]), EPS));
        s += fmaxf(ap - an + MARGIN, 0.f);
    }
    red[tid] = s;
    __syncthreads();
    for (int off = blockDim.x >> 1; off; off >>= 1) {
        if (tid < off) red[tid] += red[tid + off];
        __syncthreads();
    }
    if (tid == 0) out[0] = red[0] / (float)n;
}

extern "C" void kernel_launch(void* const* d_in, const int* in_sizes, int n_in,
                              void* d_out, int out_size) {
    const float* X    = (const float*)d_in[0];
    const int*   traw = (const int*)d_in[1];
    float* out = (float*)d_out;
    int n = in_sizes[1];
    int d = in_sizes[0] / n;

    int dynBytes = (d / KC) * 16384 + 2 * 16384;   // A persistent + B double buffer
    cudaFuncSetAttribute(dist_mma_kernel,
                         cudaFuncAttributeMaxDynamicSharedMemorySize, dynBytes);

    label_kernel<<<1, 256>>>(traw, n);

    int warpsPerBlock = 8;
    int nb = (n + warpsPerBlock - 1) / warpsPerBlock;
    sq_kernel<<<nb, warpsPerBlock * 32>>>(X, n, d);

    init_kernel<<<(n + 255) / 256, 256>>>(n);

    dim3 grid(n / TM, COLSPLIT);
    dist_mma_kernel<<<grid, 256, dynBytes>>>(X, n, d);

    loss_kernel<<<1, 1024>>>(n, out);
}

// round 11
// speedup vs baseline: 13.2501x; 2.2155x over previous
#include <cuda_runtime.h>
#include <cuda_fp16.h>
#include <math_constants.h>
#include <cstdint>

#define NMAX 16384
#define DMAX 512
#define MARGIN 0.3f
#define EPS 1e-12f

#define TM 128
#define TN 256
#define COLSPLIT 2

__device__ float  g_sq[NMAX];
__device__ int    g_lab[NMAX];
__device__ int    g_ap_bits[NMAX];
__device__ int    g_an_bits[NMAX];
__device__ __half g_xh[(size_t)NMAX * DMAX];

// ---------------- PTX helpers ----------------
__device__ __forceinline__ uint32_t smem_u32(const void* p) {
    uint32_t a;
    asm("{ .reg .u64 t; cvta.to.shared.u64 t, %1; cvt.u32.u64 %0, t; }"
        : "=r"(a) : "l"(p));
    return a;
}
#define CP_ASYNC16(dst, src) \
    asm volatile("cp.async.cg.shared.global [%0], [%1], 16;" \
                 :: "r"(dst), "l"(src) : "memory")
#define CP_COMMIT() asm volatile("cp.async.commit_group;" ::: "memory")
#define CP_WAIT1()  asm volatile("cp.async.wait_group 1;" ::: "memory")

__device__ __forceinline__ void ldsm_x4(uint32_t* r, uint32_t addr) {
    asm volatile("ldmatrix.sync.aligned.m8n8.x4.shared.b16 {%0,%1,%2,%3}, [%4];"
                 : "=r"(r[0]), "=r"(r[1]), "=r"(r[2]), "=r"(r[3]) : "r"(addr));
}
__device__ __forceinline__ void mma_f16(float* c, uint32_t a0, uint32_t a1,
                                        uint32_t a2, uint32_t a3,
                                        uint32_t b0, uint32_t b1) {
    asm volatile(
        "mma.sync.aligned.m16n8k16.row.col.f32.f16.f16.f32 "
        "{%0,%1,%2,%3}, {%4,%5,%6,%7}, {%8,%9}, {%0,%1,%2,%3};"
        : "+f"(c[0]), "+f"(c[1]), "+f"(c[2]), "+f"(c[3])
        : "r"(a0), "r"(a1), "r"(a2), "r"(a3), "r"(b0), "r"(b1));
}

// ---- canonicalize targets (int32 or int64 on disk) into g_lab as int32 ----
__global__ void label_kernel(const int* __restrict__ traw, int n) {
    __shared__ int odd_nonzero;
    if (threadIdx.x == 0) odd_nonzero = 0;
    __syncthreads();
    int m = (n < 128) ? n : 128;
    for (int i = threadIdx.x; i < m; i += blockDim.x)
        if (traw[2 * i + 1] != 0) atomicOr(&odd_nonzero, 1);
    __syncthreads();
    bool is64 = (odd_nonzero == 0);
    for (int i = threadIdx.x; i < n; i += blockDim.x)
        g_lab[i] = is64 ? traw[2 * i] : traw[i];
}

// ---------------- fp32 -> fp16 conversion (one pass) ----------------
__global__ void convert_kernel(const float* __restrict__ X, int total4) {
    int i = blockIdx.x * blockDim.x + threadIdx.x;
    if (i >= total4) return;
    float4 v = ((const float4*)X)[i];
    __half2* o = (__half2*)g_xh;
    o[2 * i]     = __floats2half2_rn(v.x, v.y);
    o[2 * i + 1] = __floats2half2_rn(v.z, v.w);
}

// ---------------- squared norms (exact fp32) ----------------
__global__ void sq_kernel(const float* __restrict__ X, int n, int d) {
    int warp = (blockIdx.x * blockDim.x + threadIdx.x) >> 5;
    int lane = threadIdx.x & 31;
    if (warp >= n) return;
    const float4* row = (const float4*)(X + (size_t)warp * d);
    float s = 0.f;
    for (int k = lane; k < d / 4; k += 32) {
        float4 v = row[k];
        s = fmaf(v.x, v.x, s); s = fmaf(v.y, v.y, s);
        s = fmaf(v.z, v.z, s); s = fmaf(v.w, v.w, s);
    }
    #pragma unroll
    for (int off = 16; off; off >>= 1)
        s += __shfl_xor_sync(0xffffffffu, s, off);
    if (lane == 0) g_sq[warp] = s;
}

__global__ void init_kernel(int n) {
    int i = blockIdx.x * blockDim.x + threadIdx.x;
    if (i < n) { g_ap_bits[i] = 0; g_an_bits[i] = 0x7f800000; }
}

// --------- fused fp16 mma gram + d^2 + hardest pos/neg ----------
// A persistent (TM x d fp16), B double-buffered via cp.async, ldmatrix frags.
__global__ __launch_bounds__(256, 1)
void dist_mma_kernel(const float* __restrict__ X, int n, int d) {
    extern __shared__ char dyn[];
    __shared__ int   tCs[TN];
    __shared__ float sCs[TN];
    __shared__ int   tRs[TM];
    __shared__ float sRs[TM];

    const int tid  = threadIdx.x;          // 256 threads = 8 warps
    const int wid  = tid >> 5;
    const int lane = tid & 31;
    const int wm   = wid & 1;              // 2 warps along M (64 rows each)
    const int wn   = wid >> 1;             // 4 warps along N (64 cols each)
    const int gID  = lane >> 2;
    const int tig  = lane & 3;

    const int rowBase = blockIdx.x * TM;
    const int colBase = blockIdx.y * (n / COLSPLIT);
    const int nJt  = (n / COLSPLIT) / TN;
    const int nStA = d / 64;               // 64-half K stages (8 for d=512)
    const int total = nJt * nStA;

    const uint32_t dynA = smem_u32(dyn);
    const uint32_t dynB = dynA + nStA * 16384;
    const __half* Xh = g_xh;

    // ---------------- prologue fills ----------------
    // A: all stages (persistent).  idx = row(128) x unit(8 x 16B)
    for (int st = 0; st < nStA; st++) {
        #pragma unroll
        for (int u = 0; u < 4; u++) {
            int idx = u * 256 + tid;
            int r = idx >> 3, q = idx & 7;
            uint32_t dst = dynA + st * 16384 + r * 128 + ((q * 16) ^ ((r & 7) << 4));
            const __half* src = Xh + (size_t)(rowBase + r) * d + st * 64 + q * 8;
            CP_ASYNC16(dst, src);
        }
    }
    // B stage 0 (buf 0): 256 rows x 8 units
    {
        #pragma unroll
        for (int u = 0; u < 8; u++) {
            int idx = u * 256 + tid;
            int r = idx >> 3, q = idx & 7;
            uint32_t dst = dynB + r * 128 + ((q * 16) ^ ((r & 7) << 4));
            const __half* src = Xh + (size_t)(colBase + r) * d + q * 8;
            CP_ASYNC16(dst, src);
        }
    }
    CP_COMMIT();           // group: A + B0
    // B stage 1 (buf 1)
    if (total > 1) {
        int jt2 = 1 / nStA, kc2 = 1 % nStA;
        int cT2 = colBase + jt2 * TN;
        #pragma unroll
        for (int u = 0; u < 8; u++) {
            int idx = u * 256 + tid;
            int r = idx >> 3, q = idx & 7;
            uint32_t dst = dynB + 32768 + r * 128 + ((q * 16) ^ ((r & 7) << 4));
            const __half* src = Xh + (size_t)(cT2 + r) * d + kc2 * 64 + q * 8;
            CP_ASYNC16(dst, src);
        }
    }
    CP_COMMIT();

    // row metadata into shared
    if (tid < TM) {
        tRs[tid] = g_lab[rowBase + tid];
        sRs[tid] = g_sq[rowBase + tid];
    }

    // frag address precompute
    const int xorv = (lane & 7) << 4;
    const uint32_t aRowOff = (uint32_t)(wm * 64 + (lane & 15)) * 128;
    const uint32_t bRowOff = (uint32_t)(wn * 64 + ((lane >> 4) & 1) * 8 + (lane & 7)) * 128;
    int kA[4], kB[4];
    #pragma unroll
    for (int blk = 0; blk < 4; blk++) {
        kA[blk] = (blk * 32 + (lane >> 4) * 16) ^ xorv;
        kB[blk] = (blk * 32 + ((lane >> 3) & 1) * 16) ^ xorv;
    }

    float acc[4][8][4];
    #pragma unroll
    for (int ma = 0; ma < 4; ma++)
        #pragma unroll
        for (int na = 0; na < 8; na++)
            #pragma unroll
            for (int f = 0; f < 4; f++) acc[ma][na][f] = 0.f;

    float apd2[8], and2[8];
    #pragma unroll
    for (int i = 0; i < 8; i++) { apd2[i] = 0.f; and2[i] = CUDART_INF_F; }

    int kcIdx = 0, jt = 0;
    for (int s = 0; s < total; s++) {
        const int cTile = colBase + jt * TN;
        CP_WAIT1();
        __syncthreads();                    // fill(s) visible to all warps

        if (kcIdx == 0) {
            tCs[tid] = g_lab[cTile + tid];
            sCs[tid] = g_sq[cTile + tid];
        }

        // ---- MMA over 4 k16 blocks of this stage ----
        const uint32_t Ast = dynA + kcIdx * 16384 + aRowOff;
        const uint32_t Bst = dynB + (s & 1) * 32768 + bRowOff;
        #pragma unroll
        for (int blk = 0; blk < 4; blk++) {
            uint32_t a[4][4], b[4][4];
            #pragma unroll
            for (int ma = 0; ma < 4; ma++)
                ldsm_x4(a[ma], Ast + ma * 2048 + kA[blk]);
            #pragma unroll
            for (int p = 0; p < 4; p++)
                ldsm_x4(b[p], Bst + p * 2048 + kB[blk]);
            #pragma unroll
            for (int ma = 0; ma < 4; ma++)
                #pragma unroll
                for (int p = 0; p < 4; p++) {
                    mma_f16(acc[ma][2 * p],     a[ma][0], a[ma][1], a[ma][2], a[ma][3],
                            b[p][0], b[p][1]);
                    mma_f16(acc[ma][2 * p + 1], a[ma][0], a[ma][1], a[ma][2], a[ma][3],
                            b[p][2], b[p][3]);
                }
        }

        // ---- epilogue at last k-stage of this jt ----
        if (kcIdx == nStA - 1) {
            #pragma unroll
            for (int ma = 0; ma < 4; ma++) {
                #pragma unroll
                for (int h = 0; h < 2; h++) {
                    int rloc = wm * 64 + ma * 16 + gID + 8 * h;
                    int rg   = rowBase + rloc;
                    int rT   = tRs[rloc];
                    float rS = sRs[rloc];
                    int ridx = ma * 2 + h;
                    #pragma unroll
                    for (int na = 0; na < 8; na++)
                        #pragma unroll
                        for (int j = 0; j < 2; j++) {
                            int col = wn * 64 + na * 8 + tig * 2 + j;
                            int cg  = cTile + col;
                            float d2 = rS + sCs[col] - 2.f * acc[ma][na][2 * h + j];
                            if (cg == rg) d2 = EPS;
                            d2 = fmaxf(d2, EPS);
                            if (rT == tCs[col]) apd2[ridx] = fmaxf(apd2[ridx], d2);
                            else                and2[ridx] = fminf(and2[ridx], d2);
                            acc[ma][na][2 * h + j] = 0.f;
                        }
                }
            }
        }

        __syncthreads();                    // all warps done with buf (s&1)
        // ---- issue fill for stage s+2 into buf (s&1) ----
        int s2 = s + 2;
        if (s2 < total) {
            int jt2 = s2 / nStA, kc2 = s2 % nStA;
            int cT2 = colBase + jt2 * TN;
            #pragma unroll
            for (int u = 0; u < 8; u++) {
                int idx = u * 256 + tid;
                int r = idx >> 3, q = idx & 7;
                uint32_t dst = dynB + (s2 & 1) * 32768 + r * 128 +
                               ((q * 16) ^ ((r & 7) << 4));
                const __half* src = Xh + (size_t)(cT2 + r) * d + kc2 * 64 + q * 8;
                CP_ASYNC16(dst, src);
            }
        }
        CP_COMMIT();

        if (++kcIdx == nStA) { kcIdx = 0; jt++; }
    }

    // reduce across the quad (same rows, different cols per tig)
    #pragma unroll
    for (int off = 1; off <= 2; off <<= 1)
        #pragma unroll
        for (int i = 0; i < 8; i++) {
            apd2[i] = fmaxf(apd2[i], __shfl_xor_sync(0xffffffffu, apd2[i], off));
            and2[i] = fminf(and2[i], __shfl_xor_sync(0xffffffffu, and2[i], off));
        }
    if (tig == 0) {
        #pragma unroll
        for (int ma = 0; ma < 4; ma++)
            #pragma unroll
            for (int h = 0; h < 2; h++) {
                int rg = rowBase + wm * 64 + ma * 16 + gID + 8 * h;
                atomicMax(&g_ap_bits[rg], __float_as_int(apd2[ma * 2 + h]));
                atomicMin(&g_an_bits[rg], __float_as_int(and2[ma * 2 + h]));
            }
    }
}

// ---------------- final mean(relu(sqrt(ap2) - sqrt(an2) + margin)) --------
__global__ void loss_kernel(int n, float* __restrict__ out) {
    __shared__ float red[1024];
    int tid = threadIdx.x;
    float s = 0.f;
    for (int i = tid; i < n; i += blockDim.x) {
        float ap = sqrtf(fmaxf(__int_as_float(g_ap_bits[i]), EPS));
        float an = sqrtf(fmaxf(__int_as_float(g_an_bits[i]), EPS));
        s += fmaxf(ap - an + MARGIN, 0.f);
    }
    red[tid] = s;
    __syncthreads();
    for (int off = blockDim.x >> 1; off; off >>= 1) {
        if (tid < off) red[tid] += red[tid + off];
        __syncthreads();
    }
    if (tid == 0) out[0] = red[0] / (float)n;
}

extern "C" void kernel_launch(void* const* d_in, const int* in_sizes, int n_in,
                              void* d_out, int out_size) {
    const float* X    = (const float*)d_in[0];
    const int*   traw = (const int*)d_in[1];
    float* out = (float*)d_out;
    int n = in_sizes[1];
    int d = in_sizes[0] / n;

    int nStA = d / 64;
    int dynBytes = nStA * 16384 + 2 * 32768;   // A persistent + B double buffer
    cudaFuncSetAttribute(dist_mma_kernel,
                         cudaFuncAttributeMaxDynamicSharedMemorySize, dynBytes);

    label_kernel<<<1, 256>>>(traw, n);

    int total4 = n * d / 4;
    convert_kernel<<<(total4 + 255) / 256, 256>>>(X, total4);

    int warpsPerBlock = 8;
    int nb = (n + warpsPerBlock - 1) / warpsPerBlock;
    sq_kernel<<<nb, warpsPerBlock * 32>>>(X, n, d);

    init_kernel<<<(n + 255) / 256, 256>>>(n);

    dim3 grid(n / TM, COLSPLIT);
    dist_mma_kernel<<<grid, 256, dynBytes>>>(X, n, d);

    loss_kernel<<<1, 1024>>>(n, out);
}